// round 14
// baseline (speedup 1.0000x reference)
#include <cuda_runtime.h>

// Per-block f64 partial contributions to Pi = 0.5*U - W.
__device__ double g_part[16384];
// Completion counter for the fused final reduction (reset each replay).
__device__ unsigned int g_done = 0;

// 16B-aligned u_phys scratch: (u0, u1, u2, 0) per node.
__device__ float4 g_u[1048576];

// f32 warp reduce -> f64 block reduce (8 warps). Result on thread 0.
__device__ __forceinline__ double block_reduce_f32_to_f64(float v) {
    #pragma unroll
    for (int o = 16; o > 0; o >>= 1)
        v += __shfl_xor_sync(0xffffffffu, v, o);
    __shared__ double sh[8];
    int lane = threadIdx.x & 31;
    int wid  = threadIdx.x >> 5;
    if (lane == 0) sh[wid] = (double)v;
    __syncthreads();
    double r = 0.0;
    if (wid == 0) {
        double t = (lane < 8) ? sh[lane] : 0.0;
        #pragma unroll
        for (int o = 4; o > 0; o >>= 1)
            t += __shfl_xor_sync(0xffffffffu, t, o);
        r = t;
    }
    return r;
}

// ---------------- node kernel: 3072 floats (1024 nodes) / block ----------------
__global__ void __launch_bounds__(256) node_kernel(
        const float4* __restrict__ pred4,
        const float4* __restrict__ fext4,
        float* __restrict__ out_u,
        const float* __restrict__ ux_c,
        const float* __restrict__ uz_c,
        const float* __restrict__ th_c,
        int n_flat, int n_nodes) {
    const float s0 = ux_c[0], s1 = uz_c[0], s2 = th_c[0];
    const int tid = threadIdx.x;
    __shared__ float su[3072];

    const int F0 = blockIdx.x * 3072;
    float wacc = 0.0f;

    #pragma unroll
    for (int k = 0; k < 3; k++) {
        int g = (F0 >> 2) + k * 256 + tid;
        int flat0 = 4 * g;
        if (flat0 + 3 < n_flat) {
            float4 p = __ldcs(&pred4[g]);
            float4 f = __ldcs(&fext4[g]);
            int m = flat0 % 3;
            float ca, cb, cc;
            if (m == 0)      { ca = s0; cb = s1; cc = s2; }
            else if (m == 1) { ca = s1; cb = s2; cc = s0; }
            else             { ca = s2; cb = s0; cc = s1; }
            float u0 = p.x * ca;
            float u1 = p.y * cb;
            float u2 = p.z * cc;
            float u3 = p.w * ca;
            *(float4*)(su + (flat0 - F0)) = make_float4(u0, u1, u2, u3);
            wacc += f.x * u0 + f.y * u1 + f.z * u2 + f.w * u3;
        } else if (flat0 < n_flat) {
            const float* pr = (const float*)pred4;
            const float* fe = (const float*)fext4;
            for (int j = flat0; j < n_flat; j++) {
                int m = j % 3;
                float sc = (m == 0) ? s0 : ((m == 1) ? s1 : s2);
                float u = pr[j] * sc;
                su[j - F0] = u;
                wacc += fe[j] * u;
            }
        }
    }
    __syncthreads();

    #pragma unroll
    for (int k = 0; k < 12; k++) {
        int idx = F0 + k * 256 + tid;
        if (idx < n_flat) __stcs(out_u + idx, su[idx - F0]);
    }

    const int Nbase = blockIdx.x * 1024;
    #pragma unroll
    for (int k = 0; k < 4; k++) {
        int ln = k * 256 + tid;
        int j = Nbase + ln;
        if (j < n_nodes)
            g_u[j] = make_float4(su[3 * ln], su[3 * ln + 1], su[3 * ln + 2], 0.0f);
    }

    double bs = block_reduce_f32_to_f64(wacc);
    if (tid == 0) g_part[blockIdx.x] = -bs;   // contributes -W
}

// ---------------- element kernel + fused final reduce ----------------
// 1024 elems / block, 4 elems / thread, block-strided (coalesced streams).
__global__ void __launch_bounds__(256) elem_kernel(
        const void* __restrict__ conn,
        const float* __restrict__ Lv,
        const float* __restrict__ Ev,
        const float* __restrict__ Av,
        const float* __restrict__ Iv,
        const float* __restrict__ dirs,
        float* __restrict__ out,
        const float* __restrict__ ux_c,
        const float* __restrict__ F_c,
        int n_elem, int part_off, int total_parts, int n_blocks,
        long long n_nodes) {

    __shared__ int s_c64;
    if (threadIdx.x == 0) {
        const long long* c64 = (const long long*)conn;
        int ok = 1;
        #pragma unroll
        for (int k = 0; k < 8; k++) {
            long long v = c64[k];
            if (v < 0 || v >= n_nodes) ok = 0;
        }
        s_c64 = ok;
    }
    __syncthreads();
    const int conn64 = s_c64;

    const int tid  = threadIdx.x;
    const int base = blockIdx.x * 1024;

    // Coalesced index loads for 4 elements.
    int ia[4], ib[4];
    if (conn64) {
        const uint4* c = (const uint4*)conn;
        #pragma unroll
        for (int k = 0; k < 4; k++) {
            int e = base + k * 256 + tid;
            if (e < n_elem) { uint4 w = __ldcs(c + e); ia[k] = (int)w.x; ib[k] = (int)w.z; }
            else            { ia[k] = 0; ib[k] = 0; }
        }
    } else {
        const int2* c = (const int2*)conn;
        #pragma unroll
        for (int k = 0; k < 4; k++) {
            int e = base + k * 256 + tid;
            if (e < n_elem) { int2 w = __ldcs(c + e); ia[k] = w.x; ib[k] = w.y; }
            else            { ia[k] = 0; ib[k] = 0; }
        }
    }

    // Issue all 8 gathers before any consumption (g_u L2-resident).
    float4 A[4], B[4];
    #pragma unroll
    for (int k = 0; k < 4; k++) {
        A[k] = g_u[ia[k]];
        B[k] = g_u[ib[k]];
    }

    float qacc = 0.0f;
    #pragma unroll
    for (int k = 0; k < 4; k++) {
        int e = base + k * 256 + tid;
        if (e < n_elem) {
            float L  = __ldcs(Lv + e);
            float E  = __ldcs(Ev + e);
            float EA = E * __ldcs(Av + e);
            float EI = E * __ldcs(Iv + e);
            float c  = __ldcs(dirs + 3 * (size_t)e + 0);
            float s  = __ldcs(dirs + 3 * (size_t)e + 2);

            float u_A =  c * A[k].x + s * A[k].y;
            float w_A = -s * A[k].x + c * A[k].y;
            float t_A = -A[k].z;
            float u_B =  c * B[k].x + s * B[k].y;
            float w_B = -s * B[k].x + c * B[k].y;
            float t_B = -B[k].z;

            float inv   = __fdividef(1.0f, L);
            float ea_l  = EA * inv;
            float ei_l  = EI * inv;
            float ei_l2 = ei_l * inv;
            float ei_l3 = ei_l2 * inv;

            float du = u_A - u_B;
            float dw = w_A - w_B;
            float ts = t_A + t_B;

            qacc += ea_l * du * du
                  + 12.0f * ei_l3 * dw * dw
                  + 12.0f * ei_l2 * dw * ts
                  + 4.0f * ei_l * (t_A * t_A + t_B * t_B + t_A * t_B);
        }
    }

    double bs = block_reduce_f32_to_f64(qacc);

    // ---- fused final reduction (cheap fencing: thread 0 only) ----
    __shared__ unsigned int s_last;
    if (tid == 0) {
        g_part[part_off + blockIdx.x] = 0.5 * bs;   // +0.5*U
        __threadfence();                            // release this store
        unsigned int old = atomicAdd(&g_done, 1u);
        s_last = (old == (unsigned int)(n_blocks - 1)) ? 1u : 0u;
    }
    __syncthreads();
    if (s_last) {
        __threadfence();                            // acquire (1 block only)
        double acc = 0.0;
        for (int k = tid; k < total_parts; k += 256)
            acc += g_part[k];
        #pragma unroll
        for (int o = 16; o > 0; o >>= 1)
            acc += __shfl_xor_sync(0xffffffffu, acc, o);
        __shared__ double shd[8];
        int lane = tid & 31;
        int wid  = tid >> 5;
        if (lane == 0) shd[wid] = acc;
        __syncthreads();
        if (wid == 0) {
            double t = (lane < 8) ? shd[lane] : 0.0;
            #pragma unroll
            for (int o = 4; o > 0; o >>= 1)
                t += __shfl_xor_sync(0xffffffffu, t, o);
            if (lane == 0) {
                double E_c = fmax((double)(F_c[0] * ux_c[0]), 1e-30);
                out[0] = (float)(t / E_c);
                g_done = 0;                // reset for next replay
            }
        }
    }
}

extern "C" void kernel_launch(void* const* d_in, const int* in_sizes, int n_in,
                              void* d_out, int out_size) {
    const float* pred  = (const float*)d_in[0];
    const float* fext  = (const float*)d_in[1];
    const void*  conn  = d_in[2];
    const float* Lv    = (const float*)d_in[3];
    const float* Ev    = (const float*)d_in[4];
    const float* Av    = (const float*)d_in[5];
    const float* Iv    = (const float*)d_in[6];
    const float* dirs  = (const float*)d_in[7];
    const float* ux_c  = (const float*)d_in[8];
    const float* uz_c  = (const float*)d_in[9];
    const float* th_c  = (const float*)d_in[10];
    const float* F_c   = (const float*)d_in[11];

    float* out = (float*)d_out;   // [0] = Pi_norm, [1..3N] = u_phys flat

    int n_flat  = in_sizes[0];
    int n_nodes = n_flat / 3;
    int n_elem  = in_sizes[3];

    int nb = (n_flat + 3071) / 3072;     // 1024 nodes / block
    int eb = (n_elem + 1023) / 1024;     // 1024 elems / block
    int total_parts = nb + eb;

    node_kernel<<<nb, 256>>>((const float4*)pred, (const float4*)fext,
                             out + 1, ux_c, uz_c, th_c, n_flat, n_nodes);
    elem_kernel<<<eb, 256>>>(conn, Lv, Ev, Av, Iv, dirs,
                             out, ux_c, F_c,
                             n_elem, nb, total_parts, eb, (long long)n_nodes);
}

// round 15
// speedup vs baseline: 1.1543x; 1.1543x over previous
#include <cuda_runtime.h>

// Per-block f64 partial contributions to Pi = 0.5*U - W.
__device__ double g_part[16384];
// Completion counter for the fused final reduction (reset each replay).
__device__ unsigned int g_done = 0;

// 16B-aligned u_phys scratch: (u0, u1, u2, 0) per node.
__device__ float4 g_u[1048576];

// f32 warp reduce -> f64 block reduce (8 warps). Result on thread 0.
__device__ __forceinline__ double block_reduce_f32_to_f64(float v) {
    #pragma unroll
    for (int o = 16; o > 0; o >>= 1)
        v += __shfl_xor_sync(0xffffffffu, v, o);
    __shared__ double sh[8];
    int lane = threadIdx.x & 31;
    int wid  = threadIdx.x >> 5;
    if (lane == 0) sh[wid] = (double)v;
    __syncthreads();
    double r = 0.0;
    if (wid == 0) {
        double t = (lane < 8) ? sh[lane] : 0.0;
        #pragma unroll
        for (int o = 4; o > 0; o >>= 1)
            t += __shfl_xor_sync(0xffffffffu, t, o);
        r = t;
    }
    return r;
}

// ---------------- node kernel: 3072 floats (1024 nodes) / block ----------------
__global__ void __launch_bounds__(256) node_kernel(
        const float4* __restrict__ pred4,
        const float4* __restrict__ fext4,
        float* __restrict__ out_u,
        const float* __restrict__ ux_c,
        const float* __restrict__ uz_c,
        const float* __restrict__ th_c,
        int n_flat, int n_nodes) {
    const float s0 = ux_c[0], s1 = uz_c[0], s2 = th_c[0];
    const int tid = threadIdx.x;
    __shared__ float su[3072];

    const int F0 = blockIdx.x * 3072;
    float wacc = 0.0f;

    #pragma unroll
    for (int k = 0; k < 3; k++) {
        int g = (F0 >> 2) + k * 256 + tid;
        int flat0 = 4 * g;
        if (flat0 + 3 < n_flat) {
            float4 p = __ldcs(&pred4[g]);
            float4 f = __ldcs(&fext4[g]);
            int m = flat0 % 3;
            float ca, cb, cc;
            if (m == 0)      { ca = s0; cb = s1; cc = s2; }
            else if (m == 1) { ca = s1; cb = s2; cc = s0; }
            else             { ca = s2; cb = s0; cc = s1; }
            float u0 = p.x * ca;
            float u1 = p.y * cb;
            float u2 = p.z * cc;
            float u3 = p.w * ca;
            *(float4*)(su + (flat0 - F0)) = make_float4(u0, u1, u2, u3);
            wacc += f.x * u0 + f.y * u1 + f.z * u2 + f.w * u3;
        } else if (flat0 < n_flat) {
            const float* pr = (const float*)pred4;
            const float* fe = (const float*)fext4;
            for (int j = flat0; j < n_flat; j++) {
                int m = j % 3;
                float sc = (m == 0) ? s0 : ((m == 1) ? s1 : s2);
                float u = pr[j] * sc;
                su[j - F0] = u;
                wacc += fe[j] * u;
            }
        }
    }
    __syncthreads();

    #pragma unroll
    for (int k = 0; k < 12; k++) {
        int idx = F0 + k * 256 + tid;
        if (idx < n_flat) __stcs(out_u + idx, su[idx - F0]);
    }

    const int Nbase = blockIdx.x * 1024;
    #pragma unroll
    for (int k = 0; k < 4; k++) {
        int ln = k * 256 + tid;
        int j = Nbase + ln;
        if (j < n_nodes)
            g_u[j] = make_float4(su[3 * ln], su[3 * ln + 1], su[3 * ln + 2], 0.0f);
    }

    double bs = block_reduce_f32_to_f64(wacc);
    if (tid == 0) g_part[blockIdx.x] = -bs;   // contributes -W
}

// ---------------- element kernel + fused final reduce ----------------
// 512 elems / block, 2 elems / thread (register-light, ~92% occupancy).
__global__ void __launch_bounds__(256) elem_kernel(
        const void* __restrict__ conn,
        const float* __restrict__ Lv,
        const float* __restrict__ Ev,
        const float* __restrict__ Av,
        const float* __restrict__ Iv,
        const float* __restrict__ dirs,
        float* __restrict__ out,
        const float* __restrict__ ux_c,
        const float* __restrict__ F_c,
        int n_elem, int part_off, int total_parts, int n_blocks,
        long long n_nodes) {

    __shared__ int s_c64;
    if (threadIdx.x == 0) {
        const long long* c64 = (const long long*)conn;
        int ok = 1;
        #pragma unroll
        for (int k = 0; k < 8; k++) {
            long long v = c64[k];
            if (v < 0 || v >= n_nodes) ok = 0;
        }
        s_c64 = ok;
    }
    __syncthreads();
    const int conn64 = s_c64;

    const int tid  = threadIdx.x;
    const int base = blockIdx.x * 512;
    const int e0 = base + tid;
    const int e1 = base + 256 + tid;

    int ia0 = 0, ib0 = 0, ia1 = 0, ib1 = 0;
    if (conn64) {
        const uint4* c = (const uint4*)conn;
        if (e0 < n_elem) { uint4 w = __ldcs(c + e0); ia0 = (int)w.x; ib0 = (int)w.z; }
        if (e1 < n_elem) { uint4 w = __ldcs(c + e1); ia1 = (int)w.x; ib1 = (int)w.z; }
    } else {
        const int2* c = (const int2*)conn;
        if (e0 < n_elem) { int2 w = __ldcs(c + e0); ia0 = w.x; ib0 = w.y; }
        if (e1 < n_elem) { int2 w = __ldcs(c + e1); ia1 = w.x; ib1 = w.y; }
    }

    float4 A0 = g_u[ia0];
    float4 B0 = g_u[ib0];
    float4 A1 = g_u[ia1];
    float4 B1 = g_u[ib1];

    float qacc = 0.0f;
    #pragma unroll
    for (int k = 0; k < 2; k++) {
        int e = (k == 0) ? e0 : e1;
        float4 A = (k == 0) ? A0 : A1;
        float4 B = (k == 0) ? B0 : B1;
        if (e < n_elem) {
            float L  = __ldcs(Lv + e);
            float E  = __ldcs(Ev + e);
            float EA = E * __ldcs(Av + e);
            float EI = E * __ldcs(Iv + e);
            float c  = __ldcs(dirs + 3 * (size_t)e + 0);
            float s  = __ldcs(dirs + 3 * (size_t)e + 2);

            float u_A =  c * A.x + s * A.y;
            float w_A = -s * A.x + c * A.y;
            float t_A = -A.z;
            float u_B =  c * B.x + s * B.y;
            float w_B = -s * B.x + c * B.y;
            float t_B = -B.z;

            float inv   = __fdividef(1.0f, L);
            float ea_l  = EA * inv;
            float ei_l  = EI * inv;
            float ei_l2 = ei_l * inv;
            float ei_l3 = ei_l2 * inv;

            float du = u_A - u_B;
            float dw = w_A - w_B;
            float ts = t_A + t_B;

            qacc += ea_l * du * du
                  + 12.0f * ei_l3 * dw * dw
                  + 12.0f * ei_l2 * dw * ts
                  + 4.0f * ei_l * (t_A * t_A + t_B * t_B + t_A * t_B);
        }
    }

    double bs = block_reduce_f32_to_f64(qacc);

    // ---- fused final reduction (thread-0-only release fence) ----
    __shared__ unsigned int s_last;
    if (tid == 0) {
        g_part[part_off + blockIdx.x] = 0.5 * bs;   // +0.5*U
        __threadfence();                            // release this store
        unsigned int old = atomicAdd(&g_done, 1u);
        s_last = (old == (unsigned int)(n_blocks - 1)) ? 1u : 0u;
    }
    __syncthreads();
    if (s_last) {
        __threadfence();                            // acquire (1 block only)
        double acc = 0.0;
        for (int k = tid; k < total_parts; k += 256)
            acc += g_part[k];
        #pragma unroll
        for (int o = 16; o > 0; o >>= 1)
            acc += __shfl_xor_sync(0xffffffffu, acc, o);
        __shared__ double shd[8];
        int lane = tid & 31;
        int wid  = tid >> 5;
        if (lane == 0) shd[wid] = acc;
        __syncthreads();
        if (wid == 0) {
            double t = (lane < 8) ? shd[lane] : 0.0;
            #pragma unroll
            for (int o = 4; o > 0; o >>= 1)
                t += __shfl_xor_sync(0xffffffffu, t, o);
            if (lane == 0) {
                double E_c = fmax((double)(F_c[0] * ux_c[0]), 1e-30);
                out[0] = (float)(t / E_c);
                g_done = 0;                // reset for next replay
            }
        }
    }
}

extern "C" void kernel_launch(void* const* d_in, const int* in_sizes, int n_in,
                              void* d_out, int out_size) {
    const float* pred  = (const float*)d_in[0];
    const float* fext  = (const float*)d_in[1];
    const void*  conn  = d_in[2];
    const float* Lv    = (const float*)d_in[3];
    const float* Ev    = (const float*)d_in[4];
    const float* Av    = (const float*)d_in[5];
    const float* Iv    = (const float*)d_in[6];
    const float* dirs  = (const float*)d_in[7];
    const float* ux_c  = (const float*)d_in[8];
    const float* uz_c  = (const float*)d_in[9];
    const float* th_c  = (const float*)d_in[10];
    const float* F_c   = (const float*)d_in[11];

    float* out = (float*)d_out;   // [0] = Pi_norm, [1..3N] = u_phys flat

    int n_flat  = in_sizes[0];
    int n_nodes = n_flat / 3;
    int n_elem  = in_sizes[3];

    int nb = (n_flat + 3071) / 3072;    // 1024 nodes / block
    int eb = (n_elem + 511) / 512;      // 512 elems / block
    int total_parts = nb + eb;

    node_kernel<<<nb, 256>>>((const float4*)pred, (const float4*)fext,
                             out + 1, ux_c, uz_c, th_c, n_flat, n_nodes);
    elem_kernel<<<eb, 256>>>(conn, Lv, Ev, Av, Iv, dirs,
                             out, ux_c, F_c,
                             n_elem, nb, total_parts, eb, (long long)n_nodes);
}